// round 2
// baseline (speedup 1.0000x reference)
#include <cuda_runtime.h>

#define BATCH 8
#define NPTS  8192
#define NGRP  512
#define KNN   32
#define NEIGH_ATTR_OFF 393216   /* 8*512*32*3 */
#define CENTER_OFF     786432
#define CATTR_OFF      798720
#define CAP 2048

__device__ float g_center[BATCH * NGRP * 3];

// ---------------- FPS: one CTA (512 threads) per batch ----------------
// Distance formula matches XLA loop-fusion exactly: mul/add, ((dx^2+dy^2)+dz^2),
// NO fma contraction (intrinsics forbid it).
__global__ __launch_bounds__(512, 1)
void fps_kernel(const float* __restrict__ xyz, float* __restrict__ out) {
    extern __shared__ float sm[];
    float* sx = sm;
    float* sy = sm + NPTS;
    float* sz = sm + 2 * NPTS;
    __shared__ unsigned s_wv[16];
    __shared__ int s_wi[16];
    __shared__ int s_cur;
    __shared__ int s_idx[NGRP];

    const int tid = threadIdx.x;
    const int b = blockIdx.x;
    const float* base = xyz + (size_t)b * NPTS * 6;

    float px[16], py[16], pz[16], pd[16];
#pragma unroll
    for (int k = 0; k < 16; k++) {
        int p = tid + (k << 9);
        float x = __ldg(base + p * 6 + 0);
        float y = __ldg(base + p * 6 + 1);
        float z = __ldg(base + p * 6 + 2);
        px[k] = x; py[k] = y; pz[k] = z; pd[k] = 1e10f;
        sx[p] = x; sy[p] = y; sz[p] = z;
    }
    if (tid == 0) s_idx[0] = 0;
    __syncthreads();

    int cur = 0;
    const int lane = tid & 31, wid = tid >> 5;

    for (int t = 1; t < NGRP; t++) {
        float cx = sx[cur], cy = sy[cur], cz = sz[cur];
        float bv = -1.0f;
        int bi = 0;
#pragma unroll
        for (int k = 0; k < 16; k++) {
            float dx = __fsub_rn(px[k], cx);
            float dy = __fsub_rn(py[k], cy);
            float dz = __fsub_rn(pz[k], cz);
            float d = __fadd_rn(__fadd_rn(__fmul_rn(dx, dx), __fmul_rn(dy, dy)),
                                __fmul_rn(dz, dz));
            float nd = fminf(pd[k], d);
            pd[k] = nd;
            if (nd > bv) { bv = nd; bi = tid + (k << 9); }  // strict > keeps lowest idx
        }
        // warp argmax: dists >= 0 so float bits are monotonic as unsigned
        unsigned vb = __float_as_uint(bv);
        unsigned vmax = __reduce_max_sync(0xFFFFFFFFu, vb);
        int cand = (vb == vmax) ? bi : 0x7FFFFFFF;
        int wmin = __reduce_min_sync(0xFFFFFFFFu, cand);   // min idx on ties
        if (lane == 0) { s_wv[wid] = vmax; s_wi[wid] = wmin; }
        __syncthreads();
        if (wid == 0) {
            unsigned v2 = (lane < 16) ? s_wv[lane] : 0u;
            unsigned m2 = __reduce_max_sync(0xFFFFFFFFu, v2);
            int c2 = (lane < 16 && v2 == m2) ? s_wi[lane] : 0x7FFFFFFF;
            int w2 = __reduce_min_sync(0xFFFFFFFFu, c2);
            if (lane == 0) { s_cur = w2; s_idx[t] = w2; }
        }
        __syncthreads();
        cur = s_cur;
    }

    // epilogue: centers (xyz + attr)
    if (tid < NGRP) {
        int idx = s_idx[tid];
        int go = b * NGRP + tid;
        float cx = sx[idx], cy = sy[idx], cz = sz[idx];
        out[CENTER_OFF + go * 3 + 0] = cx;
        out[CENTER_OFF + go * 3 + 1] = cy;
        out[CENTER_OFF + go * 3 + 2] = cz;
        g_center[go * 3 + 0] = cx;
        g_center[go * 3 + 1] = cy;
        g_center[go * 3 + 2] = cz;
        const float* ap = base + idx * 6 + 3;
        out[CATTR_OFF + go * 3 + 0] = __ldg(ap + 0);
        out[CATTR_OFF + go * 3 + 1] = __ldg(ap + 1);
        out[CATTR_OFF + go * 3 + 2] = __ldg(ap + 2);
    }
}

// ---------------- kNN: one CTA (256 threads) per (batch, group) ----------------
// d2 = (cn - 2*dot) + xn, where dot uses a GEMM-style FMA chain (the einsum is
// lowered to dot_general -> BLAS, which accumulates with fma), while cn/xn are
// elementwise+reduce fusions -> plain mul/add.
__global__ __launch_bounds__(256)
void knn_kernel(const float* __restrict__ xyz, float* __restrict__ out) {
    __shared__ float s_c[4];
    __shared__ unsigned long long s_min[256];
    __shared__ unsigned long long s_src[64];
    __shared__ unsigned long long s_T;
    __shared__ int s_cnt;
    __shared__ unsigned long long s_cand[CAP];

    const int tid = threadIdx.x;
    const int bg = blockIdx.x;
    const int b = bg >> 9;

    if (tid == 0) {
        float cx = g_center[bg * 3 + 0];
        float cy = g_center[bg * 3 + 1];
        float cz = g_center[bg * 3 + 2];
        s_c[0] = cx; s_c[1] = cy; s_c[2] = cz;
        s_c[3] = __fadd_rn(__fadd_rn(__fmul_rn(cx, cx), __fmul_rn(cy, cy)),
                           __fmul_rn(cz, cz));
        s_cnt = 0;
    }
    __syncthreads();
    const float cx = s_c[0], cy = s_c[1], cz = s_c[2], cn = s_c[3];
    const float* base = xyz + (size_t)b * NPTS * 6;

    unsigned keys[32];
    unsigned long long mn = ~0ull;
#pragma unroll
    for (int k = 0; k < 32; k++) {
        int p = tid + (k << 8);
        float x = __ldg(base + p * 6 + 0);
        float y = __ldg(base + p * 6 + 1);
        float z = __ldg(base + p * 6 + 2);
        float xn = __fadd_rn(__fadd_rn(__fmul_rn(x, x), __fmul_rn(y, y)),
                             __fmul_rn(z, z));
        // GEMM-style fma accumulation for the einsum dot
        float dt = __fmaf_rn(cz, z, __fmaf_rn(cy, y, __fmul_rn(cx, x)));
        float d2 = __fadd_rn(__fsub_rn(cn, __fmul_rn(2.0f, dt)), xn);
        unsigned u = __float_as_uint(d2);
        unsigned key = u ^ ((unsigned)((int)u >> 31) | 0x80000000u);  // monotonic
        keys[k] = key;
        unsigned long long pk = ((unsigned long long)key << 32) | (unsigned)p;
        if (pk < mn) mn = pk;
    }
    s_min[tid] = mn;
    __syncthreads();

    if (tid < 64) {
        unsigned long long a = s_min[4 * tid + 0];
        unsigned long long b2 = s_min[4 * tid + 1];
        unsigned long long c = s_min[4 * tid + 2];
        unsigned long long d = s_min[4 * tid + 3];
        if (b2 < a) a = b2;
        if (c < a) a = c;
        if (d < a) a = d;
        s_src[tid] = a;
    }
    __syncthreads();
    if (tid < 64) {
        unsigned long long m = s_src[tid];
        int r = 0;
        for (int j = 0; j < 64; j++) r += (s_src[j] < m) ? 1 : 0;
        if (r == 31) s_T = m;   // packed keys unique -> exactly one writer
    }
    __syncthreads();
    const unsigned long long T = s_T;

#pragma unroll
    for (int k = 0; k < 32; k++) {
        unsigned long long pk =
            ((unsigned long long)keys[k] << 32) | (unsigned)(tid + (k << 8));
        if (pk <= T) {
            int pos = atomicAdd(&s_cnt, 1);
            if (pos < CAP) s_cand[pos] = pk;
        }
    }
    __syncthreads();

    int n = s_cnt;
    if (n > CAP) n = CAP;
    for (int c = tid; c < n; c += 256) {
        unsigned long long pk = s_cand[c];
        int r = 0;
        for (int j = 0; j < n; j++) r += (s_cand[j] < pk) ? 1 : 0;
        if (r < KNN) {
            int p = (int)(pk & 0xFFFFFFFFull);
            const float* pp = base + p * 6;
            size_t o = ((size_t)bg * KNN + r) * 3;
            out[o + 0] = __fsub_rn(__ldg(pp + 0), cx);
            out[o + 1] = __fsub_rn(__ldg(pp + 1), cy);
            out[o + 2] = __fsub_rn(__ldg(pp + 2), cz);
            out[NEIGH_ATTR_OFF + o + 0] = __ldg(pp + 3);
            out[NEIGH_ATTR_OFF + o + 1] = __ldg(pp + 4);
            out[NEIGH_ATTR_OFF + o + 2] = __ldg(pp + 5);
        }
    }
}

extern "C" void kernel_launch(void* const* d_in, const int* in_sizes, int n_in,
                              void* d_out, int out_size) {
    const float* xyz = (const float*)d_in[0];
    float* out = (float*)d_out;
    (void)in_sizes; (void)n_in; (void)out_size;

    cudaFuncSetAttribute(fps_kernel, cudaFuncAttributeMaxDynamicSharedMemorySize,
                         3 * NPTS * (int)sizeof(float));
    fps_kernel<<<BATCH, 512, 3 * NPTS * sizeof(float)>>>(xyz, out);
    knn_kernel<<<BATCH * NGRP, 256>>>(xyz, out);
}

// round 3
// speedup vs baseline: 1.1072x; 1.1072x over previous
#include <cuda_runtime.h>

#define BATCH 8
#define NPTS  8192
#define NGRP  512
#define KNN   32
#define NEIGH_ATTR_OFF 393216   /* 8*512*32*3 */
#define CENTER_OFF     786432
#define CATTR_OFF      798720
#define CAP 2048

__device__ float  g_center[BATCH * NGRP * 3];
__device__ float4 g_pts[BATCH * NPTS];   // {x, y, z, (x*x+y*y)+z*z} planar, coalesced

// ---- packed f32x2 helpers: IEEE rn per lane == scalar FADD/FMUL bitwise ----
__device__ __forceinline__ unsigned long long f2pack(float lo, float hi) {
    unsigned long long r;
    asm("mov.b64 %0, {%1,%2};" : "=l"(r) : "f"(lo), "f"(hi));
    return r;
}
__device__ __forceinline__ void f2unpack(unsigned long long v, float& lo, float& hi) {
    asm("mov.b64 {%0,%1}, %2;" : "=f"(lo), "=f"(hi) : "l"(v));
}
__device__ __forceinline__ unsigned long long f2add(unsigned long long a, unsigned long long b) {
    unsigned long long r;
    asm("add.rn.f32x2 %0, %1, %2;" : "=l"(r) : "l"(a), "l"(b));
    return r;
}
__device__ __forceinline__ unsigned long long f2mul(unsigned long long a, unsigned long long b) {
    unsigned long long r;
    asm("mul.rn.f32x2 %0, %1, %2;" : "=l"(r) : "l"(a), "l"(b));
    return r;
}

// ---------------- FPS: one CTA (512 threads) per batch ----------------
// Packed f32x2 distance math (exact per-lane rn), single __syncthreads per
// iteration via redundant per-warp combine over double-buffered warp results.
__global__ __launch_bounds__(512, 1)
void fps_kernel(const float* __restrict__ xyz, float* __restrict__ out) {
    extern __shared__ float sm[];
    float* sx = sm;
    float* sy = sm + NPTS;
    float* sz = sm + 2 * NPTS;
    __shared__ unsigned s_wv[2][16];
    __shared__ int s_wi[2][16];
    __shared__ int s_idx[NGRP];

    const int tid = threadIdx.x;
    const int b = blockIdx.x;
    const float* base = xyz + (size_t)b * NPTS * 6;

    float tx[16], ty[16], tz[16], pd[16];
#pragma unroll
    for (int k = 0; k < 16; k++) {
        int p = tid + (k << 9);
        float x = __ldg(base + p * 6 + 0);
        float y = __ldg(base + p * 6 + 1);
        float z = __ldg(base + p * 6 + 2);
        tx[k] = x; ty[k] = y; tz[k] = z; pd[k] = 1e10f;
        sx[p] = x; sy[p] = y; sz[p] = z;
        // planar {x,y,z,xn} for knn; xn in exact knn order (mul/add)
        float xn = __fadd_rn(__fadd_rn(__fmul_rn(x, x), __fmul_rn(y, y)),
                             __fmul_rn(z, z));
        g_pts[b * NPTS + p] = make_float4(x, y, z, xn);
    }
    // pack adjacent k (2j, 2j+1) so in-thread tie scan stays index-ascending
    unsigned long long px2[8], py2[8], pz2[8];
#pragma unroll
    for (int j = 0; j < 8; j++) {
        px2[j] = f2pack(tx[2 * j], tz[0] * 0.0f + tx[2 * j + 1]); // avoid aliasing opt
        px2[j] = f2pack(tx[2 * j], tx[2 * j + 1]);
        py2[j] = f2pack(ty[2 * j], ty[2 * j + 1]);
        pz2[j] = f2pack(tz[2 * j], tz[2 * j + 1]);
    }
    if (tid == 0) s_idx[0] = 0;
    __syncthreads();

    int cur = 0, buf = 0;
    const int lane = tid & 31, wid = tid >> 5;

    for (int t = 1; t < NGRP; t++) {
        float cx = sx[cur], cy = sy[cur], cz = sz[cur];
        unsigned long long ncx2 = f2pack(-cx, -cx);
        unsigned long long ncy2 = f2pack(-cy, -cy);
        unsigned long long ncz2 = f2pack(-cz, -cz);
        float bv = -1.0f;
        int bi = 0x7FFFFFFF;
#pragma unroll
        for (int j = 0; j < 8; j++) {
            unsigned long long dx = f2add(px2[j], ncx2);   // x + (-c) == x - c exact
            unsigned long long dy = f2add(py2[j], ncy2);
            unsigned long long dz = f2add(pz2[j], ncz2);
            unsigned long long s = f2add(f2add(f2mul(dx, dx), f2mul(dy, dy)),
                                         f2mul(dz, dz));
            float dlo, dhi;
            f2unpack(s, dlo, dhi);
            float n0 = fminf(pd[2 * j], dlo);
            pd[2 * j] = n0;
            if (n0 > bv) { bv = n0; bi = tid + ((2 * j) << 9); }
            float n1 = fminf(pd[2 * j + 1], dhi);
            pd[2 * j + 1] = n1;
            if (n1 > bv) { bv = n1; bi = tid + ((2 * j + 1) << 9); }
        }
        // warp argmax: dists >= 0 so float bits monotonic as unsigned
        unsigned vb = __float_as_uint(bv);
        unsigned vmax = __reduce_max_sync(0xFFFFFFFFu, vb);
        int cand = (vb == vmax) ? bi : 0x7FFFFFFF;
        int imin = __reduce_min_sync(0xFFFFFFFFu, cand);
        if (lane == 0) { s_wv[buf][wid] = vmax; s_wi[buf][wid] = imin; }
        __syncthreads();
        // redundant combine in every warp -> cur uniform, no second barrier
        unsigned v2 = (lane < 16) ? s_wv[buf][lane] : 0u;
        unsigned m2 = __reduce_max_sync(0xFFFFFFFFu, v2);
        int c2 = (lane < 16 && v2 == m2) ? s_wi[buf][lane] : 0x7FFFFFFF;
        cur = __reduce_min_sync(0xFFFFFFFFu, c2);
        if (tid == 0) s_idx[t] = cur;
        buf ^= 1;
    }
    __syncthreads();

    // epilogue: centers (xyz + attr)
    if (tid < NGRP) {
        int idx = s_idx[tid];
        int go = b * NGRP + tid;
        float cx = sx[idx], cy = sy[idx], cz = sz[idx];
        out[CENTER_OFF + go * 3 + 0] = cx;
        out[CENTER_OFF + go * 3 + 1] = cy;
        out[CENTER_OFF + go * 3 + 2] = cz;
        g_center[go * 3 + 0] = cx;
        g_center[go * 3 + 1] = cy;
        g_center[go * 3 + 2] = cz;
        const float* ap = base + idx * 6 + 3;
        out[CATTR_OFF + go * 3 + 0] = __ldg(ap + 0);
        out[CATTR_OFF + go * 3 + 1] = __ldg(ap + 1);
        out[CATTR_OFF + go * 3 + 2] = __ldg(ap + 2);
    }
}

// ---------------- kNN: one CTA (256 threads) per (batch, group) ----------------
// Planar float4 loads (1x LDG.128/pt). d2 = (cn - 2*dot) + xn with FMA-chain dot
// (matches dot_general/BLAS), cn/xn mul/add (matches XLA fusion).
__global__ __launch_bounds__(256)
void knn_kernel(const float* __restrict__ xyz, float* __restrict__ out) {
    __shared__ float s_c[4];
    __shared__ unsigned long long s_min[256];
    __shared__ unsigned long long s_src[64];
    __shared__ unsigned long long s_T;
    __shared__ int s_cnt;
    __shared__ unsigned long long s_cand[CAP];

    const int tid = threadIdx.x;
    const int bg = blockIdx.x;
    const int b = bg >> 9;

    if (tid == 0) {
        float cx = g_center[bg * 3 + 0];
        float cy = g_center[bg * 3 + 1];
        float cz = g_center[bg * 3 + 2];
        s_c[0] = cx; s_c[1] = cy; s_c[2] = cz;
        s_c[3] = __fadd_rn(__fadd_rn(__fmul_rn(cx, cx), __fmul_rn(cy, cy)),
                           __fmul_rn(cz, cz));
        s_cnt = 0;
    }
    __syncthreads();
    const float cx = s_c[0], cy = s_c[1], cz = s_c[2], cn = s_c[3];
    const float4* __restrict__ pts = g_pts + (size_t)b * NPTS;

    unsigned keys[32];
    unsigned long long mn = ~0ull;
#pragma unroll
    for (int k = 0; k < 32; k++) {
        int p = tid + (k << 8);
        float4 q = __ldg(pts + p);
        float dt = __fmaf_rn(cz, q.z, __fmaf_rn(cy, q.y, __fmul_rn(cx, q.x)));
        float d2 = __fadd_rn(__fsub_rn(cn, __fmul_rn(2.0f, dt)), q.w);
        unsigned u = __float_as_uint(d2);
        unsigned key = u ^ ((unsigned)((int)u >> 31) | 0x80000000u);  // monotonic
        keys[k] = key;
        unsigned long long pk = ((unsigned long long)key << 32) | (unsigned)p;
        if (pk < mn) mn = pk;
    }
    s_min[tid] = mn;
    __syncthreads();

    if (tid < 64) {
        unsigned long long a = s_min[4 * tid + 0];
        unsigned long long b2 = s_min[4 * tid + 1];
        unsigned long long c = s_min[4 * tid + 2];
        unsigned long long d = s_min[4 * tid + 3];
        if (b2 < a) a = b2;
        if (c < a) a = c;
        if (d < a) a = d;
        s_src[tid] = a;
    }
    __syncthreads();
    if (tid < 64) {
        unsigned long long m = s_src[tid];
        int r = 0;
        for (int j = 0; j < 64; j++) r += (s_src[j] < m) ? 1 : 0;
        if (r == 31) s_T = m;   // packed keys unique -> exactly one writer
    }
    __syncthreads();
    const unsigned long long T = s_T;

#pragma unroll
    for (int k = 0; k < 32; k++) {
        unsigned long long pk =
            ((unsigned long long)keys[k] << 32) | (unsigned)(tid + (k << 8));
        if (pk <= T) {
            int pos = atomicAdd(&s_cnt, 1);
            if (pos < CAP) s_cand[pos] = pk;
        }
    }
    __syncthreads();

    int n = s_cnt;
    if (n > CAP) n = CAP;
    for (int c = tid; c < n; c += 256) {
        unsigned long long pk = s_cand[c];
        int r = 0;
        for (int j = 0; j < n; j++) r += (s_cand[j] < pk) ? 1 : 0;
        if (r < KNN) {
            int p = (int)(pk & 0xFFFFFFFFull);
            const float* pp = xyz + ((size_t)b * NPTS + p) * 6;
            size_t o = ((size_t)bg * KNN + r) * 3;
            out[o + 0] = __fsub_rn(__ldg(pp + 0), cx);
            out[o + 1] = __fsub_rn(__ldg(pp + 1), cy);
            out[o + 2] = __fsub_rn(__ldg(pp + 2), cz);
            out[NEIGH_ATTR_OFF + o + 0] = __ldg(pp + 3);
            out[NEIGH_ATTR_OFF + o + 1] = __ldg(pp + 4);
            out[NEIGH_ATTR_OFF + o + 2] = __ldg(pp + 5);
        }
    }
}

extern "C" void kernel_launch(void* const* d_in, const int* in_sizes, int n_in,
                              void* d_out, int out_size) {
    const float* xyz = (const float*)d_in[0];
    float* out = (float*)d_out;
    (void)in_sizes; (void)n_in; (void)out_size;

    cudaFuncSetAttribute(fps_kernel, cudaFuncAttributeMaxDynamicSharedMemorySize,
                         3 * NPTS * (int)sizeof(float));
    fps_kernel<<<BATCH, 512, 3 * NPTS * sizeof(float)>>>(xyz, out);
    knn_kernel<<<BATCH * NGRP, 256>>>(xyz, out);
}

// round 4
// speedup vs baseline: 1.1093x; 1.0019x over previous
#include <cuda_runtime.h>

#define BATCH 8
#define NPTS  8192
#define NGRP  512
#define KNN   32
#define NEIGH_ATTR_OFF 393216   /* 8*512*32*3 */
#define CENTER_OFF     786432
#define CATTR_OFF      798720
#define CAP 2048

__device__ float  g_center[BATCH * NGRP * 3];
__device__ float4 g_pts[BATCH * NPTS];   // {x, y, z, (x*x+y*y)+z*z} planar, coalesced

// ---- packed f32x2 helpers: IEEE rn per lane == scalar FADD/FMUL bitwise ----
__device__ __forceinline__ unsigned long long f2pack(float lo, float hi) {
    unsigned long long r;
    asm("mov.b64 %0, {%1,%2};" : "=l"(r) : "f"(lo), "f"(hi));
    return r;
}
__device__ __forceinline__ void f2unpack(unsigned long long v, float& lo, float& hi) {
    asm("mov.b64 {%0,%1}, %2;" : "=f"(lo), "=f"(hi) : "l"(v));
}
__device__ __forceinline__ unsigned long long f2add(unsigned long long a, unsigned long long b) {
    unsigned long long r;
    asm("add.rn.f32x2 %0, %1, %2;" : "=l"(r) : "l"(a), "l"(b));
    return r;
}
__device__ __forceinline__ unsigned long long f2mul(unsigned long long a, unsigned long long b) {
    unsigned long long r;
    asm("mul.rn.f32x2 %0, %1, %2;" : "=l"(r) : "l"(a), "l"(b));
    return r;
}

// ---------------- FPS: one CTA (512 threads) per batch ----------------
// Packed f32x2 distance math (exact per-lane rn), single __syncthreads per
// iteration via redundant per-warp combine over double-buffered warp results.
__global__ __launch_bounds__(512, 1)
void fps_kernel(const float* __restrict__ xyz, float* __restrict__ out) {
    extern __shared__ float sm[];
    float* sx = sm;
    float* sy = sm + NPTS;
    float* sz = sm + 2 * NPTS;
    __shared__ unsigned s_wv[2][16];
    __shared__ int s_wi[2][16];
    __shared__ int s_idx[NGRP];

    const int tid = threadIdx.x;
    const int b = blockIdx.x;
    const float* base = xyz + (size_t)b * NPTS * 6;

    float tx[16], ty[16], tz[16], pd[16];
#pragma unroll
    for (int k = 0; k < 16; k++) {
        int p = tid + (k << 9);
        float x = __ldg(base + p * 6 + 0);
        float y = __ldg(base + p * 6 + 1);
        float z = __ldg(base + p * 6 + 2);
        tx[k] = x; ty[k] = y; tz[k] = z; pd[k] = 1e10f;
        sx[p] = x; sy[p] = y; sz[p] = z;
        // planar {x,y,z,xn} for knn; xn in exact knn order (mul/add)
        float xn = __fadd_rn(__fadd_rn(__fmul_rn(x, x), __fmul_rn(y, y)),
                             __fmul_rn(z, z));
        g_pts[b * NPTS + p] = make_float4(x, y, z, xn);
    }
    // pack adjacent k (2j, 2j+1) so in-thread tie scan stays index-ascending
    unsigned long long px2[8], py2[8], pz2[8];
#pragma unroll
    for (int j = 0; j < 8; j++) {
        px2[j] = f2pack(tx[2 * j], tz[0] * 0.0f + tx[2 * j + 1]); // avoid aliasing opt
        px2[j] = f2pack(tx[2 * j], tx[2 * j + 1]);
        py2[j] = f2pack(ty[2 * j], ty[2 * j + 1]);
        pz2[j] = f2pack(tz[2 * j], tz[2 * j + 1]);
    }
    if (tid == 0) s_idx[0] = 0;
    __syncthreads();

    int cur = 0, buf = 0;
    const int lane = tid & 31, wid = tid >> 5;

    for (int t = 1; t < NGRP; t++) {
        float cx = sx[cur], cy = sy[cur], cz = sz[cur];
        unsigned long long ncx2 = f2pack(-cx, -cx);
        unsigned long long ncy2 = f2pack(-cy, -cy);
        unsigned long long ncz2 = f2pack(-cz, -cz);
        float bv = -1.0f;
        int bi = 0x7FFFFFFF;
#pragma unroll
        for (int j = 0; j < 8; j++) {
            unsigned long long dx = f2add(px2[j], ncx2);   // x + (-c) == x - c exact
            unsigned long long dy = f2add(py2[j], ncy2);
            unsigned long long dz = f2add(pz2[j], ncz2);
            unsigned long long s = f2add(f2add(f2mul(dx, dx), f2mul(dy, dy)),
                                         f2mul(dz, dz));
            float dlo, dhi;
            f2unpack(s, dlo, dhi);
            float n0 = fminf(pd[2 * j], dlo);
            pd[2 * j] = n0;
            if (n0 > bv) { bv = n0; bi = tid + ((2 * j) << 9); }
            float n1 = fminf(pd[2 * j + 1], dhi);
            pd[2 * j + 1] = n1;
            if (n1 > bv) { bv = n1; bi = tid + ((2 * j + 1) << 9); }
        }
        // warp argmax: dists >= 0 so float bits monotonic as unsigned
        unsigned vb = __float_as_uint(bv);
        unsigned vmax = __reduce_max_sync(0xFFFFFFFFu, vb);
        int cand = (vb == vmax) ? bi : 0x7FFFFFFF;
        int imin = __reduce_min_sync(0xFFFFFFFFu, cand);
        if (lane == 0) { s_wv[buf][wid] = vmax; s_wi[buf][wid] = imin; }
        __syncthreads();
        // redundant combine in every warp -> cur uniform, no second barrier
        unsigned v2 = (lane < 16) ? s_wv[buf][lane] : 0u;
        unsigned m2 = __reduce_max_sync(0xFFFFFFFFu, v2);
        int c2 = (lane < 16 && v2 == m2) ? s_wi[buf][lane] : 0x7FFFFFFF;
        cur = __reduce_min_sync(0xFFFFFFFFu, c2);
        if (tid == 0) s_idx[t] = cur;
        buf ^= 1;
    }
    __syncthreads();

    // epilogue: centers (xyz + attr)
    if (tid < NGRP) {
        int idx = s_idx[tid];
        int go = b * NGRP + tid;
        float cx = sx[idx], cy = sy[idx], cz = sz[idx];
        out[CENTER_OFF + go * 3 + 0] = cx;
        out[CENTER_OFF + go * 3 + 1] = cy;
        out[CENTER_OFF + go * 3 + 2] = cz;
        g_center[go * 3 + 0] = cx;
        g_center[go * 3 + 1] = cy;
        g_center[go * 3 + 2] = cz;
        const float* ap = base + idx * 6 + 3;
        out[CATTR_OFF + go * 3 + 0] = __ldg(ap + 0);
        out[CATTR_OFF + go * 3 + 1] = __ldg(ap + 1);
        out[CATTR_OFF + go * 3 + 2] = __ldg(ap + 2);
    }
}

// ---------------- kNN: one CTA (256 threads) per (batch, group) ----------------
// Planar float4 loads (1x LDG.128/pt). d2 = (cn - 2*dot) + xn with FMA-chain dot
// (matches dot_general/BLAS), cn/xn mul/add (matches XLA fusion).
__global__ __launch_bounds__(256)
void knn_kernel(const float* __restrict__ xyz, float* __restrict__ out) {
    __shared__ float s_c[4];
    __shared__ unsigned long long s_min[256];
    __shared__ unsigned long long s_src[64];
    __shared__ unsigned long long s_T;
    __shared__ int s_cnt;
    __shared__ unsigned long long s_cand[CAP];

    const int tid = threadIdx.x;
    const int bg = blockIdx.x;
    const int b = bg >> 9;

    if (tid == 0) {
        float cx = g_center[bg * 3 + 0];
        float cy = g_center[bg * 3 + 1];
        float cz = g_center[bg * 3 + 2];
        s_c[0] = cx; s_c[1] = cy; s_c[2] = cz;
        s_c[3] = __fadd_rn(__fadd_rn(__fmul_rn(cx, cx), __fmul_rn(cy, cy)),
                           __fmul_rn(cz, cz));
        s_cnt = 0;
    }
    __syncthreads();
    const float cx = s_c[0], cy = s_c[1], cz = s_c[2], cn = s_c[3];
    const float4* __restrict__ pts = g_pts + (size_t)b * NPTS;

    unsigned keys[32];
    unsigned long long mn = ~0ull;
#pragma unroll
    for (int k = 0; k < 32; k++) {
        int p = tid + (k << 8);
        float4 q = __ldg(pts + p);
        float dt = __fmaf_rn(cz, q.z, __fmaf_rn(cy, q.y, __fmul_rn(cx, q.x)));
        float d2 = __fadd_rn(__fsub_rn(cn, __fmul_rn(2.0f, dt)), q.w);
        unsigned u = __float_as_uint(d2);
        unsigned key = u ^ ((unsigned)((int)u >> 31) | 0x80000000u);  // monotonic
        keys[k] = key;
        unsigned long long pk = ((unsigned long long)key << 32) | (unsigned)p;
        if (pk < mn) mn = pk;
    }
    s_min[tid] = mn;
    __syncthreads();

    if (tid < 64) {
        unsigned long long a = s_min[4 * tid + 0];
        unsigned long long b2 = s_min[4 * tid + 1];
        unsigned long long c = s_min[4 * tid + 2];
        unsigned long long d = s_min[4 * tid + 3];
        if (b2 < a) a = b2;
        if (c < a) a = c;
        if (d < a) a = d;
        s_src[tid] = a;
    }
    __syncthreads();
    if (tid < 64) {
        unsigned long long m = s_src[tid];
        int r = 0;
        for (int j = 0; j < 64; j++) r += (s_src[j] < m) ? 1 : 0;
        if (r == 31) s_T = m;   // packed keys unique -> exactly one writer
    }
    __syncthreads();
    const unsigned long long T = s_T;

#pragma unroll
    for (int k = 0; k < 32; k++) {
        unsigned long long pk =
            ((unsigned long long)keys[k] << 32) | (unsigned)(tid + (k << 8));
        if (pk <= T) {
            int pos = atomicAdd(&s_cnt, 1);
            if (pos < CAP) s_cand[pos] = pk;
        }
    }
    __syncthreads();

    int n = s_cnt;
    if (n > CAP) n = CAP;
    for (int c = tid; c < n; c += 256) {
        unsigned long long pk = s_cand[c];
        int r = 0;
        for (int j = 0; j < n; j++) r += (s_cand[j] < pk) ? 1 : 0;
        if (r < KNN) {
            int p = (int)(pk & 0xFFFFFFFFull);
            const float* pp = xyz + ((size_t)b * NPTS + p) * 6;
            size_t o = ((size_t)bg * KNN + r) * 3;
            out[o + 0] = __fsub_rn(__ldg(pp + 0), cx);
            out[o + 1] = __fsub_rn(__ldg(pp + 1), cy);
            out[o + 2] = __fsub_rn(__ldg(pp + 2), cz);
            out[NEIGH_ATTR_OFF + o + 0] = __ldg(pp + 3);
            out[NEIGH_ATTR_OFF + o + 1] = __ldg(pp + 4);
            out[NEIGH_ATTR_OFF + o + 2] = __ldg(pp + 5);
        }
    }
}

extern "C" void kernel_launch(void* const* d_in, const int* in_sizes, int n_in,
                              void* d_out, int out_size) {
    const float* xyz = (const float*)d_in[0];
    float* out = (float*)d_out;
    (void)in_sizes; (void)n_in; (void)out_size;

    cudaFuncSetAttribute(fps_kernel, cudaFuncAttributeMaxDynamicSharedMemorySize,
                         3 * NPTS * (int)sizeof(float));
    fps_kernel<<<BATCH, 512, 3 * NPTS * sizeof(float)>>>(xyz, out);
    knn_kernel<<<BATCH * NGRP, 256>>>(xyz, out);
}